// round 1
// baseline (speedup 1.0000x reference)
#include <cuda_runtime.h>
#include <cuda_bf16.h>
#include <math.h>

// ---------------- problem constants ----------------
#define S     4096
#define DM    768
#define FF    3072
#define HNUM  12
#define HD    64
#define WIN   256
#define CCH   16          // chunks
#define NW    8           // global tokens
#define LNUM  12
#define OUTD  128
#define SCALE 0.125f      // 1/sqrt(64)

// ---------------- scratch ----------------
__device__ float g_h   [S*DM];
__device__ float g_q   [S*DM];
__device__ float g_k   [S*DM];
__device__ float g_v   [S*DM];
__device__ float g_kg  [S*DM];
__device__ float g_vg  [S*DM];
__device__ float g_attn[S*DM];
__device__ float g_y   [S*DM];
__device__ float g_ffn [S*FF];
__device__ float g_qg  [NW*DM];

// ---------------- helpers ----------------
__device__ __forceinline__ float gelu_f(float x) {
    float x3 = x * x * x;
    return 0.5f * x * (1.0f + tanhf(0.7978845608028654f * (x + 0.044715f * x3)));
}

// ---------------- embedding + LN ----------------
__global__ void embed_kernel(const int* __restrict__ x, const float* __restrict__ we,
                             const float* __restrict__ pe, const float* __restrict__ ls,
                             const float* __restrict__ lb, float* __restrict__ h)
{
    int s = blockIdx.x;
    int tid = threadIdx.x;
    int r = s & 511, w = s >> 9;
    int id = (r == 0) ? 0 : x[w * 511 + r - 1];
    __shared__ float red[256];
    float vals[3];
    float sum = 0.f;
#pragma unroll
    for (int i = 0; i < 3; i++) {
        int d = tid + i * 256;
        vals[i] = we[(size_t)id * DM + d] + pe[s * DM + d];
        sum += vals[i];
    }
    red[tid] = sum; __syncthreads();
    for (int o = 128; o > 0; o >>= 1) { if (tid < o) red[tid] += red[tid + o]; __syncthreads(); }
    float mean = red[0] / (float)DM;
    __syncthreads();
    float vsum = 0.f;
#pragma unroll
    for (int i = 0; i < 3; i++) { float t = vals[i] - mean; vsum += t * t; }
    red[tid] = vsum; __syncthreads();
    for (int o = 128; o > 0; o >>= 1) { if (tid < o) red[tid] += red[tid + o]; __syncthreads(); }
    float rstd = rsqrtf(red[0] / (float)DM + 1e-5f);
#pragma unroll
    for (int i = 0; i < 3; i++) {
        int d = tid + i * 256;
        h[s * DM + d] = (vals[i] - mean) * rstd * ls[d] + lb[d];
    }
}

// ---------------- residual add + LN (in-place safe: each elem owned by one thread) ----------------
__global__ void add_ln_kernel(const float* __restrict__ x, const float* __restrict__ y,
                              const float* __restrict__ ls, const float* __restrict__ lb,
                              float* __restrict__ o)
{
    int s = blockIdx.x;
    int tid = threadIdx.x;
    __shared__ float red[256];
    float vals[3];
    float sum = 0.f;
#pragma unroll
    for (int i = 0; i < 3; i++) {
        int d = tid + i * 256;
        vals[i] = x[(size_t)s * DM + d] + y[(size_t)s * DM + d];
        sum += vals[i];
    }
    red[tid] = sum; __syncthreads();
    for (int off = 128; off > 0; off >>= 1) { if (tid < off) red[tid] += red[tid + off]; __syncthreads(); }
    float mean = red[0] / (float)DM;
    __syncthreads();
    float vsum = 0.f;
#pragma unroll
    for (int i = 0; i < 3; i++) { float t = vals[i] - mean; vsum += t * t; }
    red[tid] = vsum; __syncthreads();
    for (int off = 128; off > 0; off >>= 1) { if (tid < off) red[tid] += red[tid + off]; __syncthreads(); }
    float rstd = rsqrtf(red[0] / (float)DM + 1e-5f);
#pragma unroll
    for (int i = 0; i < 3; i++) {
        int d = tid + i * 256;
        o[(size_t)s * DM + d] = (vals[i] - mean) * rstd * ls[d] + lb[d];
    }
}

// ---------------- SGEMM: C = act((A@B + bias)*alpha) ----------------
// BM=128 BN=128 BK=8 TM=8 TN=8, 256 threads
__global__ __launch_bounds__(256)
void sgemm_kernel(const float* __restrict__ A, const float* __restrict__ B,
                  const float* __restrict__ bias, float* __restrict__ C,
                  int M, int N, int K, float alpha, int act)
{
    __shared__ float As[8][128];
    __shared__ float Bs[8][128];
    int tid = threadIdx.x;
    int bx = blockIdx.x, by = blockIdx.y;
    int tx = tid % 16, ty = tid / 16;

    float acc[8][8];
#pragma unroll
    for (int i = 0; i < 8; i++)
#pragma unroll
        for (int j = 0; j < 8; j++) acc[i][j] = 0.f;

    int aRow = tid / 2;
    int aCol = (tid % 2) * 4;
    int bRow = tid / 32;
    int bCol = (tid % 32) * 4;

    for (int k0 = 0; k0 < K; k0 += 8) {
        int arow_g = by * 128 + aRow;
        float4 av;
        if (arow_g < M) av = *(const float4*)(A + (size_t)arow_g * K + k0 + aCol);
        else            av = make_float4(0.f, 0.f, 0.f, 0.f);
        As[aCol + 0][aRow] = av.x;
        As[aCol + 1][aRow] = av.y;
        As[aCol + 2][aRow] = av.z;
        As[aCol + 3][aRow] = av.w;
        float4 bv = *(const float4*)(B + (size_t)(k0 + bRow) * N + bx * 128 + bCol);
        *(float4*)&Bs[bRow][bCol] = bv;
        __syncthreads();
#pragma unroll
        for (int kk = 0; kk < 8; kk++) {
            float ar[8], br[8];
#pragma unroll
            for (int i = 0; i < 8; i++) ar[i] = As[kk][ty * 8 + i];
#pragma unroll
            for (int j = 0; j < 8; j++) br[j] = Bs[kk][tx * 8 + j];
#pragma unroll
            for (int i = 0; i < 8; i++)
#pragma unroll
                for (int j = 0; j < 8; j++) acc[i][j] += ar[i] * br[j];
        }
        __syncthreads();
    }

#pragma unroll
    for (int i = 0; i < 8; i++) {
        int row = by * 128 + ty * 8 + i;
        if (row >= M) continue;
#pragma unroll
        for (int j = 0; j < 8; j++) {
            int col = bx * 128 + tx * 8 + j;
            float t = (acc[i][j] + bias[col]) * alpha;
            if (act == 1) t = gelu_f(t);
            C[(size_t)row * N + col] = t;
        }
    }
}

// ---------------- local (sliding-window + global-key) attention ----------------
// grid (CCH, HNUM), 256 threads, thread = one query row
__global__ __launch_bounds__(256, 1)
void local_attn_kernel(const float* __restrict__ q, const float* __restrict__ k,
                       const float* __restrict__ v, float* __restrict__ out)
{
    int c = blockIdx.x, hh = blockIdx.y;
    int qi = threadIdx.x;
    int qpos = c * WIN + qi;
    int hoff = hh * HD;

    float qreg[HD];
#pragma unroll
    for (int d = 0; d < HD; d++) qreg[d] = q[(size_t)qpos * DM + hoff + d];

    __shared__ float ks[16][HD];
    __shared__ float vs[16][HD];

    float m = -1e30f, l = 0.f;
    float acc[HD];
#pragma unroll
    for (int d = 0; d < HD; d++) acc[d] = 0.f;

    // ---- global keys (8, always valid) ----
    {
        int t = threadIdx.x;
        if (t < 128) {
            int g = t / 16;
            int d4 = (t % 16) * 4;
            int gpos = g * 512;
            *(float4*)&ks[g][d4] = *(const float4*)&k[(size_t)gpos * DM + hoff + d4];
            *(float4*)&vs[g][d4] = *(const float4*)&v[(size_t)gpos * DM + hoff + d4];
        }
        __syncthreads();
        float s[8];
        float tmax = m;
#pragma unroll
        for (int j = 0; j < 8; j++) {
            float a = 0.f;
#pragma unroll
            for (int d = 0; d < HD; d++) a += qreg[d] * ks[j][d];
            s[j] = a;
            tmax = fmaxf(tmax, a);
        }
        float sc = __expf(m - tmax);
        l *= sc;
#pragma unroll
        for (int d = 0; d < HD; d++) acc[d] *= sc;
#pragma unroll
        for (int j = 0; j < 8; j++) {
            float p = __expf(s[j] - tmax);
            l += p;
#pragma unroll
            for (int d = 0; d < HD; d++) acc[d] += p * vs[j][d];
        }
        m = tmax;
    }

    // ---- local window: 48 tiles of 16 keys, j in [0,768), kpos = c*256 + j - 256 ----
    for (int t0 = 0; t0 < 48; t0++) {
        int t = threadIdx.x;
        int j = t / 16;
        int d4 = (t % 16) * 4;
        int jglob = t0 * 16 + j;
        int kpos = c * WIN + jglob - WIN;
        float4 kv4 = make_float4(0.f, 0.f, 0.f, 0.f);
        float4 vv4 = make_float4(0.f, 0.f, 0.f, 0.f);
        if (kpos >= 0 && kpos < S) {
            kv4 = *(const float4*)&k[(size_t)kpos * DM + hoff + d4];
            vv4 = *(const float4*)&v[(size_t)kpos * DM + hoff + d4];
        }
        __syncthreads();   // previous tile consumed
        *(float4*)&ks[j][d4] = kv4;
        *(float4*)&vs[j][d4] = vv4;
        __syncthreads();

        float s[16];
        float tmax = m;
#pragma unroll
        for (int jj = 0; jj < 16; jj++) {
            int jg = t0 * 16 + jj;
            int kp = c * WIN + jg - WIN;
            bool valid = (jg >= qi) && (jg <= qi + 2 * WIN) && (kp >= 0) && (kp < S);
            float a = 0.f;
#pragma unroll
            for (int d = 0; d < HD; d++) a += qreg[d] * ks[jj][d];
            s[jj] = valid ? a : -1e30f;
            tmax = fmaxf(tmax, s[jj]);
        }
        float sc = __expf(m - tmax);
        l *= sc;
#pragma unroll
        for (int d = 0; d < HD; d++) acc[d] *= sc;
#pragma unroll
        for (int jj = 0; jj < 16; jj++) {
            float p = __expf(s[jj] - tmax);
            l += p;
#pragma unroll
            for (int d = 0; d < HD; d++) acc[d] += p * vs[jj][d];
        }
        m = tmax;
    }

    float inv = 1.f / l;
#pragma unroll
    for (int d = 0; d < HD; d++)
        out[(size_t)qpos * DM + hoff + d] = acc[d] * inv;
}

// ---------------- qg projection: qg[g,:] = (h[g*512,:] @ Wqg + bqg) * SCALE ----------------
__global__ void qg_kernel(const float* __restrict__ h, const float* __restrict__ Wqg,
                          const float* __restrict__ bqg, float* __restrict__ qg)
{
    int g = blockIdx.x;
    int o = blockIdx.y * 128 + threadIdx.x;
    const float* hr = h + (size_t)(g * 512) * DM;
    float a = bqg[o];
    for (int d = 0; d < DM; d++) a += hr[d] * Wqg[(size_t)d * DM + o];
    qg[g * DM + o] = a * SCALE;
}

// ---------------- global-token full attention, overwrites GPOS rows of out ----------------
// grid (NW, HNUM), 256 threads
__global__ void global_attn_kernel(const float* __restrict__ qg, const float* __restrict__ kg,
                                   const float* __restrict__ vg, float* __restrict__ out)
{
    int g = blockIdx.x, hh = blockIdx.y;
    int hoff = hh * HD;
    int tid = threadIdx.x;
    __shared__ float qs[HD];
    __shared__ float sc[S];
    __shared__ float red[256];
    if (tid < HD) qs[tid] = qg[g * DM + hoff + tid];
    __syncthreads();

    float lmax = -1e30f;
    for (int i = 0; i < 16; i++) {
        int s = i * 256 + tid;
        const float* kr = kg + (size_t)s * DM + hoff;
        float a = 0.f;
#pragma unroll
        for (int d = 0; d < HD; d++) a += qs[d] * kr[d];
        sc[s] = a;
        lmax = fmaxf(lmax, a);
    }
    red[tid] = lmax; __syncthreads();
    for (int o = 128; o > 0; o >>= 1) { if (tid < o) red[tid] = fmaxf(red[tid], red[tid + o]); __syncthreads(); }
    float mx = red[0]; __syncthreads();

    float lsum = 0.f;
    for (int i = 0; i < 16; i++) {
        int s = i * 256 + tid;
        float p = __expf(sc[s] - mx);
        sc[s] = p;
        lsum += p;
    }
    red[tid] = lsum; __syncthreads();
    for (int o = 128; o > 0; o >>= 1) { if (tid < o) red[tid] += red[tid + o]; __syncthreads(); }
    float inv = 1.f / red[0]; __syncthreads();

    int d = tid & 63;
    int part = tid >> 6;
    float a = 0.f;
    for (int s = part * 1024; s < (part + 1) * 1024; s++)
        a += sc[s] * vg[(size_t)s * DM + hoff + d];
    red[tid] = a; __syncthreads();
    if (tid < 64) {
        float r = red[tid] + red[tid + 64] + red[tid + 128] + red[tid + 192];
        out[(size_t)(g * 512) * DM + hoff + d] = r * inv;
    }
}

// ---------------- output head: out[g,o] = h[g*512,:] @ Wout + bout ----------------
__global__ void head_kernel(const float* __restrict__ h, const float* __restrict__ Wout,
                            const float* __restrict__ bout, float* __restrict__ out)
{
    int g = blockIdx.x;
    int o = threadIdx.x; // 128
    const float* hr = h + (size_t)(g * 512) * DM;
    float a = bout[o];
    for (int d = 0; d < DM; d++) a += hr[d] * Wout[(size_t)d * OUTD + o];
    out[g * OUTD + o] = a;
}

// ---------------- driver ----------------
extern "C" void kernel_launch(void* const* d_in, const int* in_sizes, int n_in,
                              void* d_out, int out_size)
{
    (void)in_sizes; (void)n_in; (void)out_size;
    const int*   x        = (const int*)  d_in[0];
    const float* word_emb = (const float*)d_in[1];
    const float* pos_emb  = (const float*)d_in[2];
    const float* emb_ln_s = (const float*)d_in[3];
    const float* emb_ln_b = (const float*)d_in[4];
    const float* Wq  = (const float*)d_in[5];   const float* bq  = (const float*)d_in[6];
    const float* Wk  = (const float*)d_in[7];   const float* bk  = (const float*)d_in[8];
    const float* Wv  = (const float*)d_in[9];   const float* bv  = (const float*)d_in[10];
    const float* Wo  = (const float*)d_in[11];  const float* bo  = (const float*)d_in[12];
    const float* Wqg = (const float*)d_in[13];  const float* bqg = (const float*)d_in[14];
    const float* Wkg = (const float*)d_in[15];  const float* bkg = (const float*)d_in[16];
    const float* Wvg = (const float*)d_in[17];  const float* bvg = (const float*)d_in[18];
    const float* ln1s= (const float*)d_in[19];  const float* ln1b= (const float*)d_in[20];
    const float* W1  = (const float*)d_in[21];  const float* b1  = (const float*)d_in[22];
    const float* W2  = (const float*)d_in[23];  const float* b2  = (const float*)d_in[24];
    const float* ln2s= (const float*)d_in[25];  const float* ln2b= (const float*)d_in[26];
    const float* Wout= (const float*)d_in[27];  const float* bout= (const float*)d_in[28];
    float* out = (float*)d_out;

    float *h, *q, *k, *v, *kg, *vg, *attn, *y, *ffn, *qg;
    cudaGetSymbolAddress((void**)&h,    g_h);
    cudaGetSymbolAddress((void**)&q,    g_q);
    cudaGetSymbolAddress((void**)&k,    g_k);
    cudaGetSymbolAddress((void**)&v,    g_v);
    cudaGetSymbolAddress((void**)&kg,   g_kg);
    cudaGetSymbolAddress((void**)&vg,   g_vg);
    cudaGetSymbolAddress((void**)&attn, g_attn);
    cudaGetSymbolAddress((void**)&y,    g_y);
    cudaGetSymbolAddress((void**)&ffn,  g_ffn);
    cudaGetSymbolAddress((void**)&qg,   g_qg);

    embed_kernel<<<S, 256>>>(x, word_emb, pos_emb, emb_ln_s, emb_ln_b, h);

    dim3 gridP(DM / 128, S / 128);    // 6 x 32
    dim3 gridF1(FF / 128, S / 128);   // 24 x 32
    dim3 gridF2(DM / 128, S / 128);   // 6 x 32
    dim3 gridAtt(CCH, HNUM);          // 16 x 12
    dim3 gridQg(NW, DM / 128);        // 8 x 6
    dim3 gridGA(NW, HNUM);            // 8 x 12

    for (int l = 0; l < LNUM; l++) {
        size_t wO = (size_t)l * DM * DM;
        size_t bO = (size_t)l * DM;
        size_t w1O = (size_t)l * DM * FF;
        size_t b1O = (size_t)l * FF;
        size_t w2O = (size_t)l * FF * DM;

        sgemm_kernel<<<gridP, 256>>>(h, Wq + wO, bq + bO, q, S, DM, DM, SCALE, 0);
        sgemm_kernel<<<gridP, 256>>>(h, Wk + wO, bk + bO, k, S, DM, DM, 1.0f, 0);
        sgemm_kernel<<<gridP, 256>>>(h, Wv + wO, bv + bO, v, S, DM, DM, 1.0f, 0);
        local_attn_kernel<<<gridAtt, 256>>>(q, k, v, attn);

        qg_kernel<<<gridQg, 128>>>(h, Wqg + wO, bqg + bO, qg);
        sgemm_kernel<<<gridP, 256>>>(h, Wkg + wO, bkg + bO, kg, S, DM, DM, 1.0f, 0);
        sgemm_kernel<<<gridP, 256>>>(h, Wvg + wO, bvg + bO, vg, S, DM, DM, 1.0f, 0);
        global_attn_kernel<<<gridGA, 256>>>(qg, kg, vg, attn);

        sgemm_kernel<<<gridP, 256>>>(attn, Wo + wO, bo + bO, y, S, DM, DM, 1.0f, 0);
        add_ln_kernel<<<S, 256>>>(h, y, ln1s + bO, ln1b + bO, h);

        sgemm_kernel<<<gridF1, 256>>>(h, W1 + w1O, b1 + b1O, ffn, S, FF, DM, 1.0f, 1);
        sgemm_kernel<<<gridF2, 256>>>(ffn, W2 + w2O, b2 + bO, y, S, DM, FF, 1.0f, 0);
        add_ln_kernel<<<S, 256>>>(h, y, ln2s + bO, ln2b + bO, h);
    }

    head_kernel<<<NW, 128>>>(h, Wout, bout, out);
}

// round 3
// speedup vs baseline: 1.9703x; 1.9703x over previous
#include <cuda_runtime.h>
#include <cuda_bf16.h>
#include <math.h>
#include <stdint.h>

// ---------------- problem constants ----------------
#define S     4096
#define DM    768
#define FF    3072
#define HNUM  12
#define HD    64
#define WIN   256
#define CCH   16          // chunks
#define NW    8           // global tokens
#define LNUM  12
#define OUTD  128
#define SCALE 0.125f      // 1/sqrt(64)

// ---------------- scratch ----------------
__device__ float g_h   [S*DM];
__device__ float g_q   [S*DM];
__device__ float g_k   [S*DM];
__device__ float g_v   [S*DM];
__device__ float g_kg  [S*DM];
__device__ float g_vg  [S*DM];
__device__ float g_attn[S*DM];
__device__ float g_y   [S*DM];
__device__ float g_ffn [S*FF];
__device__ float g_qg  [NW*DM];

// ---------------- helpers ----------------
__device__ __forceinline__ float gelu_f(float x) {
    float x3 = x * x * x;
    return 0.5f * x * (1.0f + tanhf(0.7978845608028654f * (x + 0.044715f * x3)));
}

__device__ __forceinline__ uint32_t f2tf32(float f) {
    uint32_t r;
    asm("cvt.rna.tf32.f32 %0, %1;" : "=r"(r) : "f"(f));
    return r;
}

// ---------------- embedding + LN ----------------
__global__ void embed_kernel(const int* __restrict__ x, const float* __restrict__ we,
                             const float* __restrict__ pe, const float* __restrict__ ls,
                             const float* __restrict__ lb, float* __restrict__ h)
{
    int s = blockIdx.x;
    int tid = threadIdx.x;
    int r = s & 511, w = s >> 9;
    int id = (r == 0) ? 0 : x[w * 511 + r - 1];
    __shared__ float red[256];
    float vals[3];
    float sum = 0.f;
#pragma unroll
    for (int i = 0; i < 3; i++) {
        int d = tid + i * 256;
        vals[i] = we[(size_t)id * DM + d] + pe[s * DM + d];
        sum += vals[i];
    }
    red[tid] = sum; __syncthreads();
    for (int o = 128; o > 0; o >>= 1) { if (tid < o) red[tid] += red[tid + o]; __syncthreads(); }
    float mean = red[0] / (float)DM;
    __syncthreads();
    float vsum = 0.f;
#pragma unroll
    for (int i = 0; i < 3; i++) { float t = vals[i] - mean; vsum += t * t; }
    red[tid] = vsum; __syncthreads();
    for (int o = 128; o > 0; o >>= 1) { if (tid < o) red[tid] += red[tid + o]; __syncthreads(); }
    float rstd = rsqrtf(red[0] / (float)DM + 1e-5f);
#pragma unroll
    for (int i = 0; i < 3; i++) {
        int d = tid + i * 256;
        h[s * DM + d] = (vals[i] - mean) * rstd * ls[d] + lb[d];
    }
}

// ---------------- residual add + LN ----------------
__global__ void add_ln_kernel(const float* __restrict__ x, const float* __restrict__ y,
                              const float* __restrict__ ls, const float* __restrict__ lb,
                              float* __restrict__ o)
{
    int s = blockIdx.x;
    int tid = threadIdx.x;
    __shared__ float red[256];
    float vals[3];
    float sum = 0.f;
#pragma unroll
    for (int i = 0; i < 3; i++) {
        int d = tid + i * 256;
        vals[i] = x[(size_t)s * DM + d] + y[(size_t)s * DM + d];
        sum += vals[i];
    }
    red[tid] = sum; __syncthreads();
    for (int off = 128; off > 0; off >>= 1) { if (tid < off) red[tid] += red[tid + off]; __syncthreads(); }
    float mean = red[0] / (float)DM;
    __syncthreads();
    float vsum = 0.f;
#pragma unroll
    for (int i = 0; i < 3; i++) { float t = vals[i] - mean; vsum += t * t; }
    red[tid] = vsum; __syncthreads();
    for (int off = 128; off > 0; off >>= 1) { if (tid < off) red[tid] += red[tid + off]; __syncthreads(); }
    float rstd = rsqrtf(red[0] / (float)DM + 1e-5f);
#pragma unroll
    for (int i = 0; i < 3; i++) {
        int d = tid + i * 256;
        o[(size_t)s * DM + d] = (vals[i] - mean) * rstd * ls[d] + lb[d];
    }
}

// ---------------- tf32 tensor-core GEMM ----------------
// C[M,N] = act((A[M,K] @ B[K,N] + bias) * alpha); A,B fp32 in gmem, tf32 in smem.
// BM=128 BN=128 BK=32, 256 threads = 8 warps, warp tile 64x32 (2x4 warp grid)
__global__ __launch_bounds__(256)
void tgemm_kernel(const float* __restrict__ A, const float* __restrict__ B,
                  const float* __restrict__ bias, float* __restrict__ C,
                  int M, int N, int K, float alpha, int act)
{
    __shared__ __align__(16) uint32_t As[128][36];  // stride 36: bank=(4*row+col)%32 distinct
    __shared__ __align__(16) uint32_t Bs[32][136];  // stride 136: bank=(8*row+col)%32 distinct

    const int tid  = threadIdx.x;
    const int lane = tid & 31;
    const int warp = tid >> 5;
    const int wm = warp >> 2;     // 0..1
    const int wn = warp & 3;      // 0..3
    const int g  = lane >> 2;     // groupID  0..7
    const int t  = lane & 3;      // thread-in-group 0..3

    const int bRow = blockIdx.y * 128;
    const int bCol = blockIdx.x * 128;

    float acc[4][4][4];
#pragma unroll
    for (int i = 0; i < 4; i++)
#pragma unroll
        for (int j = 0; j < 4; j++)
#pragma unroll
            for (int r = 0; r < 4; r++) acc[i][j][r] = 0.f;

    // A staging: thread -> row = tid/2, cols [(tid&1)*16, +16)
    const int a_row = tid >> 1;
    const int a_col = (tid & 1) * 16;

    for (int k0 = 0; k0 < K; k0 += 32) {
        // stage A tile (fp32 -> tf32)
        const float* Ag = A + (size_t)(bRow + a_row) * K + k0 + a_col;
#pragma unroll
        for (int c = 0; c < 16; c += 4) {
            float4 v = *(const float4*)(Ag + c);
            uint4 pk;
            pk.x = f2tf32(v.x); pk.y = f2tf32(v.y);
            pk.z = f2tf32(v.z); pk.w = f2tf32(v.w);
            *(uint4*)&As[a_row][a_col + c] = pk;
        }
        // stage B tile (fp32 -> tf32): 32 rows x 128 cols = 1024 float4, 4 per thread
#pragma unroll
        for (int p = 0; p < 4; p++) {
            int f4 = p * 256 + tid;
            int r = f4 >> 5;            // 0..31
            int c = (f4 & 31) * 4;      // 0..124
            float4 v = *(const float4*)(B + (size_t)(k0 + r) * N + bCol + c);
            uint4 pk;
            pk.x = f2tf32(v.x); pk.y = f2tf32(v.y);
            pk.z = f2tf32(v.z); pk.w = f2tf32(v.w);
            *(uint4*)&Bs[r][c] = pk;
        }
        __syncthreads();

#pragma unroll
        for (int kk = 0; kk < 32; kk += 8) {
            // A fragments: m16n8k8, per mi: a0(g,t) a1(g+8,t) a2(g,t+4) a3(g+8,t+4)
            uint32_t af[4][4];
#pragma unroll
            for (int mi = 0; mi < 4; mi++) {
                int r0 = wm * 64 + mi * 16 + g;
                af[mi][0] = As[r0][kk + t];
                af[mi][1] = As[r0 + 8][kk + t];
                af[mi][2] = As[r0][kk + t + 4];
                af[mi][3] = As[r0 + 8][kk + t + 4];
            }
            // B fragments: b0(k=t, n=g) b1(k=t+4, n=g)
            uint32_t bf[4][2];
#pragma unroll
            for (int ni = 0; ni < 4; ni++) {
                int cn = wn * 32 + ni * 8 + g;
                bf[ni][0] = Bs[kk + t][cn];
                bf[ni][1] = Bs[kk + t + 4][cn];
            }
#pragma unroll
            for (int mi = 0; mi < 4; mi++)
#pragma unroll
                for (int ni = 0; ni < 4; ni++) {
                    asm volatile(
                        "mma.sync.aligned.m16n8k8.row.col.f32.tf32.tf32.f32 "
                        "{%0,%1,%2,%3}, {%4,%5,%6,%7}, {%8,%9}, {%0,%1,%2,%3};"
                        : "+f"(acc[mi][ni][0]), "+f"(acc[mi][ni][1]),
                          "+f"(acc[mi][ni][2]), "+f"(acc[mi][ni][3])
                        : "r"(af[mi][0]), "r"(af[mi][1]), "r"(af[mi][2]), "r"(af[mi][3]),
                          "r"(bf[ni][0]), "r"(bf[ni][1]));
                }
        }
        __syncthreads();
    }

    // epilogue
#pragma unroll
    for (int mi = 0; mi < 4; mi++) {
        int row0 = bRow + wm * 64 + mi * 16 + g;
#pragma unroll
        for (int ni = 0; ni < 4; ni++) {
            int col = bCol + wn * 32 + ni * 8 + t * 2;
            float b0 = bias[col], b1 = bias[col + 1];
            float v0 = (acc[mi][ni][0] + b0) * alpha;
            float v1 = (acc[mi][ni][1] + b1) * alpha;
            float v2 = (acc[mi][ni][2] + b0) * alpha;
            float v3 = (acc[mi][ni][3] + b1) * alpha;
            if (act == 1) { v0 = gelu_f(v0); v1 = gelu_f(v1); v2 = gelu_f(v2); v3 = gelu_f(v3); }
            *(float2*)&C[(size_t)row0 * N + col]       = make_float2(v0, v1);
            *(float2*)&C[(size_t)(row0 + 8) * N + col] = make_float2(v2, v3);
        }
    }
}

// ---------------- local (sliding-window + global-key) attention ----------------
__global__ __launch_bounds__(256, 1)
void local_attn_kernel(const float* __restrict__ q, const float* __restrict__ k,
                       const float* __restrict__ v, float* __restrict__ out)
{
    int c = blockIdx.x, hh = blockIdx.y;
    int qi = threadIdx.x;
    int qpos = c * WIN + qi;
    int hoff = hh * HD;

    float qreg[HD];
#pragma unroll
    for (int d = 0; d < HD; d++) qreg[d] = q[(size_t)qpos * DM + hoff + d];

    __shared__ float ks[16][HD];
    __shared__ float vs[16][HD];

    float m = -1e30f, l = 0.f;
    float acc[HD];
#pragma unroll
    for (int d = 0; d < HD; d++) acc[d] = 0.f;

    // ---- global keys (8) ----
    {
        int tt = threadIdx.x;
        if (tt < 128) {
            int gg = tt / 16;
            int d4 = (tt % 16) * 4;
            int gpos = gg * 512;
            *(float4*)&ks[gg][d4] = *(const float4*)&k[(size_t)gpos * DM + hoff + d4];
            *(float4*)&vs[gg][d4] = *(const float4*)&v[(size_t)gpos * DM + hoff + d4];
        }
        __syncthreads();
        float s[8];
        float tmax = m;
#pragma unroll
        for (int j = 0; j < 8; j++) {
            float a = 0.f;
#pragma unroll
            for (int d = 0; d < HD; d++) a += qreg[d] * ks[j][d];
            s[j] = a;
            tmax = fmaxf(tmax, a);
        }
        float sc = __expf(m - tmax);
        l *= sc;
#pragma unroll
        for (int d = 0; d < HD; d++) acc[d] *= sc;
#pragma unroll
        for (int j = 0; j < 8; j++) {
            float p = __expf(s[j] - tmax);
            l += p;
#pragma unroll
            for (int d = 0; d < HD; d++) acc[d] += p * vs[j][d];
        }
        m = tmax;
    }

    // ---- local window: 48 tiles of 16 keys ----
    for (int t0 = 0; t0 < 48; t0++) {
        int tt = threadIdx.x;
        int j = tt / 16;
        int d4 = (tt % 16) * 4;
        int jglob = t0 * 16 + j;
        int kpos = c * WIN + jglob - WIN;
        float4 kv4 = make_float4(0.f, 0.f, 0.f, 0.f);
        float4 vv4 = make_float4(0.f, 0.f, 0.f, 0.f);
        if (kpos >= 0 && kpos < S) {
            kv4 = *(const float4*)&k[(size_t)kpos * DM + hoff + d4];
            vv4 = *(const float4*)&v[(size_t)kpos * DM + hoff + d4];
        }
        __syncthreads();
        *(float4*)&ks[j][d4] = kv4;
        *(float4*)&vs[j][d4] = vv4;
        __syncthreads();

        float s[16];
        float tmax = m;
#pragma unroll
        for (int jj = 0; jj < 16; jj++) {
            int jg = t0 * 16 + jj;
            int kp = c * WIN + jg - WIN;
            bool valid = (jg >= qi) && (jg <= qi + 2 * WIN) && (kp >= 0) && (kp < S);
            float a = 0.f;
#pragma unroll
            for (int d = 0; d < HD; d++) a += qreg[d] * ks[jj][d];
            s[jj] = valid ? a : -1e30f;
            tmax = fmaxf(tmax, s[jj]);
        }
        float sc = __expf(m - tmax);
        l *= sc;
#pragma unroll
        for (int d = 0; d < HD; d++) acc[d] *= sc;
#pragma unroll
        for (int jj = 0; jj < 16; jj++) {
            float p = __expf(s[jj] - tmax);
            l += p;
#pragma unroll
            for (int d = 0; d < HD; d++) acc[d] += p * vs[jj][d];
        }
        m = tmax;
    }

    float inv = 1.f / l;
#pragma unroll
    for (int d = 0; d < HD; d++)
        out[(size_t)qpos * DM + hoff + d] = acc[d] * inv;
}

// ---------------- qg projection ----------------
__global__ void qg_kernel(const float* __restrict__ h, const float* __restrict__ Wqg,
                          const float* __restrict__ bqg, float* __restrict__ qg)
{
    int g = blockIdx.x;
    int o = blockIdx.y * 128 + threadIdx.x;
    const float* hr = h + (size_t)(g * 512) * DM;
    float a = bqg[o];
    for (int d = 0; d < DM; d++) a += hr[d] * Wqg[(size_t)d * DM + o];
    qg[g * DM + o] = a * SCALE;
}

// ---------------- global-token full attention ----------------
__global__ void global_attn_kernel(const float* __restrict__ qg, const float* __restrict__ kg,
                                   const float* __restrict__ vg, float* __restrict__ out)
{
    int g = blockIdx.x, hh = blockIdx.y;
    int hoff = hh * HD;
    int tid = threadIdx.x;
    __shared__ float qs[HD];
    __shared__ float sc[S];
    __shared__ float red[256];
    if (tid < HD) qs[tid] = qg[g * DM + hoff + tid];
    __syncthreads();

    float lmax = -1e30f;
    for (int i = 0; i < 16; i++) {
        int s = i * 256 + tid;
        const float* kr = kg + (size_t)s * DM + hoff;
        float a = 0.f;
#pragma unroll
        for (int d = 0; d < HD; d++) a += qs[d] * kr[d];
        sc[s] = a;
        lmax = fmaxf(lmax, a);
    }
    red[tid] = lmax; __syncthreads();
    for (int o = 128; o > 0; o >>= 1) { if (tid < o) red[tid] = fmaxf(red[tid], red[tid + o]); __syncthreads(); }
    float mx = red[0]; __syncthreads();

    float lsum = 0.f;
    for (int i = 0; i < 16; i++) {
        int s = i * 256 + tid;
        float p = __expf(sc[s] - mx);
        sc[s] = p;
        lsum += p;
    }
    red[tid] = lsum; __syncthreads();
    for (int o = 128; o > 0; o >>= 1) { if (tid < o) red[tid] += red[tid + o]; __syncthreads(); }
    float inv = 1.f / red[0]; __syncthreads();

    int d = tid & 63;
    int part = tid >> 6;
    float a = 0.f;
    for (int s = part * 1024; s < (part + 1) * 1024; s++)
        a += sc[s] * vg[(size_t)s * DM + hoff + d];
    red[tid] = a; __syncthreads();
    if (tid < 64) {
        float r = red[tid] + red[tid + 64] + red[tid + 128] + red[tid + 192];
        out[(size_t)(g * 512) * DM + hoff + d] = r * inv;
    }
}

// ---------------- output head ----------------
__global__ void head_kernel(const float* __restrict__ h, const float* __restrict__ Wout,
                            const float* __restrict__ bout, float* __restrict__ out)
{
    int g = blockIdx.x;
    int o = threadIdx.x; // 128
    const float* hr = h + (size_t)(g * 512) * DM;
    float a = bout[o];
    for (int d = 0; d < DM; d++) a += hr[d] * Wout[(size_t)d * OUTD + o];
    out[g * OUTD + o] = a;
}

// ---------------- driver ----------------
extern "C" void kernel_launch(void* const* d_in, const int* in_sizes, int n_in,
                              void* d_out, int out_size)
{
    (void)in_sizes; (void)n_in; (void)out_size;
    const int*   x        = (const int*)  d_in[0];
    const float* word_emb = (const float*)d_in[1];
    const float* pos_emb  = (const float*)d_in[2];
    const float* emb_ln_s = (const float*)d_in[3];
    const float* emb_ln_b = (const float*)d_in[4];
    const float* Wq  = (const float*)d_in[5];   const float* bq  = (const float*)d_in[6];
    const float* Wk  = (const float*)d_in[7];   const float* bk  = (const float*)d_in[8];
    const float* Wv  = (const float*)d_in[9];   const float* bv  = (const float*)d_in[10];
    const float* Wo  = (const float*)d_in[11];  const float* bo  = (const float*)d_in[12];
    const float* Wqg = (const float*)d_in[13];  const float* bqg = (const float*)d_in[14];
    const float* Wkg = (const float*)d_in[15];  const float* bkg = (const float*)d_in[16];
    const float* Wvg = (const float*)d_in[17];  const float* bvg = (const float*)d_in[18];
    const float* ln1s= (const float*)d_in[19];  const float* ln1b= (const float*)d_in[20];
    const float* W1  = (const float*)d_in[21];  const float* b1  = (const float*)d_in[22];
    const float* W2  = (const float*)d_in[23];  const float* b2  = (const float*)d_in[24];
    const float* ln2s= (const float*)d_in[25];  const float* ln2b= (const float*)d_in[26];
    const float* Wout= (const float*)d_in[27];  const float* bout= (const float*)d_in[28];
    float* out = (float*)d_out;

    float *h, *q, *k, *v, *kg, *vg, *attn, *y, *ffn, *qg;
    cudaGetSymbolAddress((void**)&h,    g_h);
    cudaGetSymbolAddress((void**)&q,    g_q);
    cudaGetSymbolAddress((void**)&k,    g_k);
    cudaGetSymbolAddress((void**)&v,    g_v);
    cudaGetSymbolAddress((void**)&kg,   g_kg);
    cudaGetSymbolAddress((void**)&vg,   g_vg);
    cudaGetSymbolAddress((void**)&attn, g_attn);
    cudaGetSymbolAddress((void**)&y,    g_y);
    cudaGetSymbolAddress((void**)&ffn,  g_ffn);
    cudaGetSymbolAddress((void**)&qg,   g_qg);

    embed_kernel<<<S, 256>>>(x, word_emb, pos_emb, emb_ln_s, emb_ln_b, h);

    dim3 gridP(DM / 128, S / 128);    // 6 x 32
    dim3 gridF1(FF / 128, S / 128);   // 24 x 32
    dim3 gridF2(DM / 128, S / 128);   // 6 x 32
    dim3 gridAtt(CCH, HNUM);          // 16 x 12
    dim3 gridQg(NW, DM / 128);        // 8 x 6
    dim3 gridGA(NW, HNUM);            // 8 x 12

    for (int l = 0; l < LNUM; l++) {
        size_t wO  = (size_t)l * DM * DM;
        size_t bO  = (size_t)l * DM;
        size_t w1O = (size_t)l * DM * FF;
        size_t b1O = (size_t)l * FF;
        size_t w2O = (size_t)l * FF * DM;

        tgemm_kernel<<<gridP, 256>>>(h, Wq + wO, bq + bO, q, S, DM, DM, SCALE, 0);
        tgemm_kernel<<<gridP, 256>>>(h, Wk + wO, bk + bO, k, S, DM, DM, 1.0f, 0);
        tgemm_kernel<<<gridP, 256>>>(h, Wv + wO, bv + bO, v, S, DM, DM, 1.0f, 0);
        local_attn_kernel<<<gridAtt, 256>>>(q, k, v, attn);

        qg_kernel<<<gridQg, 128>>>(h, Wqg + wO, bqg + bO, qg);
        tgemm_kernel<<<gridP, 256>>>(h, Wkg + wO, bkg + bO, kg, S, DM, DM, 1.0f, 0);
        tgemm_kernel<<<gridP, 256>>>(h, Wvg + wO, bvg + bO, vg, S, DM, DM, 1.0f, 0);
        global_attn_kernel<<<gridGA, 256>>>(qg, kg, vg, attn);

        tgemm_kernel<<<gridP, 256>>>(attn, Wo + wO, bo + bO, y, S, DM, DM, 1.0f, 0);
        add_ln_kernel<<<S, 256>>>(h, y, ln1s + bO, ln1b + bO, h);

        tgemm_kernel<<<gridF1, 256>>>(h, W1 + w1O, b1 + b1O, ffn, S, FF, DM, 1.0f, 1);
        tgemm_kernel<<<gridF2, 256>>>(ffn, W2 + w2O, b2 + bO, y, S, DM, FF, 1.0f, 0);
        add_ln_kernel<<<S, 256>>>(h, y, ln2s + bO, ln2b + bO, h);
    }

    head_kernel<<<NW, 128>>>(h, Wout, bout, out);
}